// round 14
// baseline (speedup 1.0000x reference)
#include <cuda_runtime.h>
#include <cuda_bf16.h>
#include <cstdint>

// Problem constants
#define BB 8
#define NN 2048
#define FF 128
#define ROWS (BB*NN)            // 16384
#define ALPHA 0.2f

// tcgen05 is only legal when the VIRTUAL arch is compute_103a/100a-class.
// The harness also compiles a plain compute_103 PTX pass where tcgen05 is
// rejected by ptxas — gate on the arch-feature macros. The #else branch is a
// full scalar fallback: a macro mismatch degrades perf, never correctness.
#if defined(__CUDA_ARCH_FEAT_SM103_ALL) || defined(__CUDA_ARCH_FEAT_SM100_ALL) || \
    defined(__CUDA_ARCH_FEAT_SM101_ALL) || defined(__CUDA_ARCH_FEAT_SM110_ALL)
#define TC_OK 1
#else
#define TC_OK 0
#endif

// ---------------- scratch (static device globals; no allocation) ----------
__device__ float    g_h[ROWS * FF];        // 8 MB  h = input @ W^T (f32)
__device__ float    g_src[ROWS];
__device__ float4   g_duv[ROWS];           // {dst, exp(dst), exp(0.2 dst), 0}
__device__ float    g_P[ROWS];             // exp(src)/Z   (-1 flag = uniform row)
__device__ float    g_Q[ROWS];             // exp(0.2 src)/Z
__device__ unsigned g_mask[ROWS * (NN/32)]; // 4 MB adjacency bitmask
__device__ __nv_bfloat16 g_hT_hi[(size_t)BB * FF * NN];  // 4 MB  h^T hi split
__device__ __nv_bfloat16 g_hT_lo[(size_t)BB * FF * NN];  // 4 MB  h^T lo split

// ---------------- packed fp32x2 helpers (FFMA2 — PTX only) ----------------
__device__ __forceinline__ unsigned long long pack2(float x, float y) {
    unsigned long long r;
    asm("mov.b64 %0, {%1, %2};" : "=l"(r) : "f"(x), "f"(y));
    return r;
}
__device__ __forceinline__ void fma2(unsigned long long& d,
                                     unsigned long long a,
                                     unsigned long long b) {
    asm("fma.rn.f32x2 %0, %1, %2, %0;" : "+l"(d) : "l"(a), "l"(b));
}
__device__ __forceinline__ float2 unpack2(unsigned long long v) {
    float2 r;
    asm("mov.b64 {%0, %1}, %2;" : "=f"(r.x), "=f"(r.y) : "l"(v));
    return r;
}

__device__ __forceinline__ uint32_t pack_bf2(__nv_bfloat16 a, __nv_bfloat16 b) {
    __nv_bfloat162 t; t.x = a; t.y = b;
    return *reinterpret_cast<uint32_t*>(&t);
}
__device__ __forceinline__ uint32_t swz128(uint32_t off) {      // SW128 swizzle
    return off ^ ((off >> 3) & 0x70u);
}
__device__ __forceinline__ uint32_t smem_u32(const void* p) {
    uint32_t a;
    asm("{ .reg .u64 t; cvta.to.shared.u64 t, %1; cvt.u32.u64 %0, t; }"
        : "=r"(a) : "l"(p));
    return a;
}
// split f32 -> bf16 hi + bf16 lo (w ~= hi + lo)
__device__ __forceinline__ void bf16_split(float w, __nv_bfloat16& h, __nv_bfloat16& l) {
    h = __float2bfloat16(w);
    l = __float2bfloat16(w - __bfloat162float(h));
}

#if TC_OK
// ---------------- tcgen05 / mbarrier helpers (sm_103a only) ---------------
__device__ __forceinline__ uint32_t elect_one_pred() {
    uint32_t pred;
    asm volatile("{\n\t.reg .pred p;\n\telect.sync _|p, 0xFFFFFFFF;\n\t"
                 "selp.b32 %0, 1, 0, p;\n\t}" : "=r"(pred));
    return pred;
}
#define TC_ALLOC(smem_addr, n) \
    asm volatile("tcgen05.alloc.cta_group::1.sync.aligned.shared::cta.b32 [%0], %1;" \
                 :: "r"(smem_addr), "r"((uint32_t)(n)) : "memory")
#define TC_DEALLOC(tmem, n) \
    asm volatile("tcgen05.dealloc.cta_group::1.sync.aligned.b32 %0, %1;" \
                 :: "r"(tmem), "r"((uint32_t)(n)))
#define TC_COMMIT(mbar) \
    asm volatile("tcgen05.commit.cta_group::1.mbarrier::arrive::one.shared::cluster.b64 [%0];" \
                 :: "r"(mbar) : "memory")
#define TC_FENCE_AFTER() asm volatile("tcgen05.fence::after_thread_sync;" ::: "memory")
#define TC_WAIT_LD()     asm volatile("tcgen05.wait::ld.sync.aligned;" ::: "memory")
#define FENCE_ASYNC()    asm volatile("fence.proxy.async.shared::cta;" ::: "memory")
#define MBAR_INIT(a, n) \
    asm volatile("mbarrier.init.shared.b64 [%0], %1;" :: "r"(a), "r"((uint32_t)(n)) : "memory")
#define MBAR_WAIT(a, ph) do {                                                     \
    uint32_t _m = (a), _p = (ph), _d;                                             \
    asm volatile("{\n\t.reg .pred p;\n\t"                                         \
        "mbarrier.try_wait.parity.acquire.cta.shared::cta.b64 p, [%1], %2;\n\t"   \
        "selp.b32 %0, 1, 0, p;\n\t}" : "=r"(_d) : "r"(_m), "r"(_p) : "memory");   \
    if (!_d) { asm volatile("{\n\t.reg .pred P1;\n\tWL_%=:\n\t"                   \
        "mbarrier.try_wait.parity.acquire.cta.shared::cta.b64 P1, [%0], %1, 0x989680;\n\t" \
        "@P1 bra.uni WD_%=;\n\tbra.uni WL_%=;\n\tWD_%=:\n\t}"                     \
        :: "r"(_m), "r"(_p) : "memory"); }                                        \
} while (0)
#define TC_LD_X32(r, tmem) \
    asm volatile("tcgen05.ld.sync.aligned.32x32b.x32.b32 " \
        "{%0,%1,%2,%3,%4,%5,%6,%7,%8,%9,%10,%11,%12,%13,%14,%15," \
        "%16,%17,%18,%19,%20,%21,%22,%23,%24,%25,%26,%27,%28,%29,%30,%31}, [%32];" \
        : "=r"((r)[0]),"=r"((r)[1]),"=r"((r)[2]),"=r"((r)[3]), \
          "=r"((r)[4]),"=r"((r)[5]),"=r"((r)[6]),"=r"((r)[7]), \
          "=r"((r)[8]),"=r"((r)[9]),"=r"((r)[10]),"=r"((r)[11]), \
          "=r"((r)[12]),"=r"((r)[13]),"=r"((r)[14]),"=r"((r)[15]), \
          "=r"((r)[16]),"=r"((r)[17]),"=r"((r)[18]),"=r"((r)[19]), \
          "=r"((r)[20]),"=r"((r)[21]),"=r"((r)[22]),"=r"((r)[23]), \
          "=r"((r)[24]),"=r"((r)[25]),"=r"((r)[26]),"=r"((r)[27]), \
          "=r"((r)[28]),"=r"((r)[29]),"=r"((r)[30]),"=r"((r)[31]) \
        : "r"(tmem))

static __device__ __forceinline__ uint64_t make_desc(uint32_t addr) {
    const uint64_t BASE = (uint64_t(2) << 61) | (uint64_t(1) << 46)
                        | (uint64_t(64) << 32) | (uint64_t(1) << 16);  // SW128 K-major
    return BASE | ((uint64_t)(addr >> 4) & 0x3FFFull);
}
// SS bf16 MMA, cta_group::1, kind::f16
__device__ __forceinline__ void mma_f16_ss(uint32_t d, uint64_t ad, uint64_t bd,
                                           uint32_t idesc, uint32_t en) {
    asm volatile("{\n\t.reg .pred p;\n\tsetp.ne.u32 p, %5, 0;\n\t"
        "tcgen05.mma.cta_group::1.kind::f16 [%0], %1, %2, %3, {%4, %4, %4, %4}, p;\n\t}"
        :: "r"(d), "l"(ad), "l"(bd), "r"(idesc), "r"(0u), "r"(en) : "memory");
}
// idesc: F32 dtype | BF16 a | BF16 b | N=128 (16<<17) | M=128 (8<<24)
#define K3_IDESC 0x8200490u
#endif  // TC_OK

// ===========================================================================
// Kernel 1: h = input @ W^T, fused with (a) src/dst projections + exp factors
// and (b) the bf16 hi/lo transposed copy g_hT (eliminates separate k1c).
// Block: 256 threads, tile 64 rows x 128 cols, one batch per block.
// ===========================================================================
__global__ __launch_bounds__(256) void k1_gemm(const float* __restrict__ input,
                                               const float* __restrict__ W,
                                               const float* __restrict__ a_src,
                                               const float* __restrict__ a_dst) {
    // aliased smem: GEMM phase uses shA(8KB)+shBt(16KB); transpose phase
    // reuses the same region as shT[64][133] (34 KB total static).
    __shared__ __align__(16) unsigned char sraw[64*133*4];
    float (*shA)[32]   = (float (*)[32])sraw;
    float (*shBt)[128] = (float (*)[128])(sraw + 64*32*4);
    float (*shT)[133]  = (float (*)[133])sraw;

    const int tid  = threadIdx.x;
    const int warp = tid >> 5;
    const int lane = tid & 31;
    const int row0 = blockIdx.x * 64;
    const int b    = row0 >> 11;
    const int j0l  = row0 & (NN-1);       // batch-local row base (BUGFIX)
    const int c0   = lane * 4;

    unsigned long long acc[8][2];
    #pragma unroll
    for (int r = 0; r < 8; ++r) { acc[r][0] = 0ull; acc[r][1] = 0ull; }

    for (int kc = 0; kc < 4; ++kc) {
        __syncthreads();
        for (int v = tid; v < 64*32; v += 256) {
            int r = v >> 5, k = v & 31;
            shA[r][k] = input[(size_t)(row0 + r) * FF + kc*32 + k];
        }
        for (int v = tid; v < 32*128; v += 256) {
            int c = v & 127, kk = v >> 7;
            shBt[kk][c] = W[(size_t)c * FF + kc*32 + kk];
        }
        __syncthreads();

        #pragma unroll 4
        for (int k = 0; k < 32; ++k) {
            ulonglong2 bv = *(const ulonglong2*)&shBt[k][c0];
            #pragma unroll
            for (int r = 0; r < 8; ++r) {
                float a = shA[warp*8 + r][k];
                unsigned long long ap = pack2(a, a);
                fma2(acc[r][0], ap, bv.x);
                fma2(acc[r][1], ap, bv.y);
            }
        }
    }

    // ---- epilogue A: g_h store + fused projections ----
    const float4 as4 = *(const float4*)&a_src[c0];
    const float4 ad4 = *(const float4*)&a_dst[c0];
    float s1[8], s2[8];
    #pragma unroll
    for (int r = 0; r < 8; ++r) {
        int row = row0 + warp*8 + r;
        float2 p0 = unpack2(acc[r][0]);
        float2 p1 = unpack2(acc[r][1]);
        *(float4*)&g_h[(size_t)row * FF + c0] = make_float4(p0.x, p0.y, p1.x, p1.y);
        s1[r] = p0.x*as4.x + p0.y*as4.y + p1.x*as4.z + p1.y*as4.w;
        s2[r] = p0.x*ad4.x + p0.y*ad4.y + p1.x*ad4.z + p1.y*ad4.w;
    }
    #pragma unroll
    for (int off = 16; off; off >>= 1) {
        #pragma unroll
        for (int r = 0; r < 8; ++r) {
            s1[r] += __shfl_xor_sync(0xffffffffu, s1[r], off);
            s2[r] += __shfl_xor_sync(0xffffffffu, s2[r], off);
        }
    }
    if (lane < 8) {
        int row = row0 + warp*8 + lane;
        float sv = s1[lane], dv = s2[lane];
        g_src[row] = sv;
        g_duv[row] = make_float4(dv, __expf(dv), __expf(ALPHA * dv), 0.f);
    }

    // ---- epilogue B: transpose + bf16 hi/lo split (replaces k1c) ----
    __syncthreads();   // all GEMM reads of shA/shBt done; safe to overwrite
    #pragma unroll
    for (int r = 0; r < 8; ++r) {
        int jl = warp*8 + r;
        float2 p0 = unpack2(acc[r][0]);
        float2 p1 = unpack2(acc[r][1]);
        shT[jl][c0 + 0] = p0.x;
        shT[jl][c0 + 1] = p0.y;
        shT[jl][c0 + 2] = p1.x;
        shT[jl][c0 + 3] = p1.y;
    }
    __syncthreads();

    // out: thread = (f = fp*64 + tid>>2, jq = tid&3 -> 16 j's) over 2 passes
    const int jq = tid & 3;
    #pragma unroll
    for (int fp = 0; fp < 2; ++fp) {
        const int f = fp*64 + (tid >> 2);
        size_t obase = ((size_t)(b*FF + f)) * NN + j0l + jq*16;   // batch-local j!
        uint32_t hw[8], lw[8];
        #pragma unroll
        for (int p = 0; p < 8; ++p) {
            float w0 = shT[jq*16 + p*2 + 0][f];
            float w1 = shT[jq*16 + p*2 + 1][f];
            __nv_bfloat16 h0, l0, h1, l1;
            bf16_split(w0, h0, l0);
            bf16_split(w1, h1, l1);
            hw[p] = pack_bf2(h0, h1);
            lw[p] = pack_bf2(l0, l1);
        }
        *(uint4*)(g_hT_hi + obase)     = make_uint4(hw[0], hw[1], hw[2], hw[3]);
        *(uint4*)(g_hT_hi + obase + 8) = make_uint4(hw[4], hw[5], hw[6], hw[7]);
        *(uint4*)(g_hT_lo + obase)     = make_uint4(lw[0], lw[1], lw[2], lw[3]);
        *(uint4*)(g_hT_lo + obase + 8) = make_uint4(lw[4], lw[5], lw[6], lw[7]);
    }
}

// ===========================================================================
// Kernel 2: adj scan -> bitmask + factorized normalizer (unchanged, proven).
// ===========================================================================
__global__ __launch_bounds__(256) void k2_stats(const int* __restrict__ adj) {
    const int warp = threadIdx.x >> 5;
    const int lane = threadIdx.x & 31;
    const int row  = blockIdx.x * 8 + warp;
    const int b    = row >> 11;
    const int i    = row & (NN-1);

    const int*    arow = adj + ((size_t)b * NN + i) * NN;
    const float4* duvb = g_duv + b * NN;
    const float   srci = g_src[row];

    float su = 0.f, sv = 0.f;
    for (int w = 0; w < NN/32; ++w) {
        int    j  = w*32 + lane;
        int    av = arow[j];
        float4 d  = __ldg(&duvb[j]);
        bool allowed = av > 0;
        unsigned bal = __ballot_sync(0xffffffffu, allowed);
        if (lane == 0) g_mask[(size_t)row * (NN/32) + w] = bal;
        if (allowed) {
            if (srci + d.x > 0.f) su += d.y;
            else                  sv += d.z;
        }
    }
    #pragma unroll
    for (int off = 16; off; off >>= 1) {
        su += __shfl_xor_sync(0xffffffffu, su, off);
        sv += __shfl_xor_sync(0xffffffffu, sv, off);
    }
    float eS  = __expf(srci);
    float eS2 = __expf(ALPHA * srci);
    float Z   = eS * su + eS2 * sv;
    if (lane == 0) {
        if (Z > 0.f) { g_P[row] = eS / Z;  g_Q[row] = eS2 / Z; }
        else         { g_P[row] = -1.f;    g_Q[row] = 0.f;     }
    }
    if (!(Z > 0.f)) {      // isolated row -> uniform over all j
        g_mask[(size_t)row * (NN/32) + lane]      = 0xffffffffu;
        g_mask[(size_t)row * (NN/32) + 32 + lane] = 0xffffffffu;
    }
}

// ===========================================================================
// Kernel 3: out = ELU( att @ h ).  Per CTA: M=128 rows x N=128 feats,
// K=2048 in 64-chunks.  tcgen05 path: A = on-the-fly weights (bf16 hi+lo),
// B = pre-split h^T; 3 MMAs per K16-step (hh+hl+lh), fp32 TMEM accum,
// double-buffered smem + mbarrier pacing.  512 threads: staging roles
// split 2x finer than R11 so the issue-bound staging phase halves.
// ===========================================================================
#define K3_CH    64                 // K per chunk
#define K3_NCH   (NN/K3_CH)         // 32 chunks
#define K3_BUFSZ 65536              // 4 tiles x 16KB per buffer
#define OFF_AHI(buf) ((buf)*K3_BUFSZ + 0)
#define OFF_ALO(buf) ((buf)*K3_BUFSZ + 16384)
#define OFF_BHI(buf) ((buf)*K3_BUFSZ + 32768)
#define OFF_BLO(buf) ((buf)*K3_BUFSZ + 49152)
#define K3_DSM_BYTES (2*K3_BUFSZ + 1024)

extern __shared__ unsigned char k3_dsm[];

__global__ __launch_bounds__(512) void k3_mma(float* __restrict__ out) {
#if TC_OK
    __shared__ float4   sduv[2][64];
    __shared__ uint32_t s_tmem;
    __shared__ __align__(8) unsigned long long s_mbar[2];

    const int tid  = threadIdx.x;
    const int wid  = tid >> 5;
    const int lid  = tid & 31;
    const int row0 = blockIdx.x * 128;
    const int b    = row0 >> 11;

    uint32_t raw = smem_u32(k3_dsm);
    uint32_t sb  = (raw + 1023) & ~1023u;
    unsigned char* base = k3_dsm + (sb - raw);
    uint32_t mb0 = smem_u32(&s_mbar[0]);
    uint32_t mb1 = smem_u32(&s_mbar[1]);

    if (wid == 0) TC_ALLOC(smem_u32(&s_tmem), 128);
    if (tid == 0) { MBAR_INIT(mb0, 1); MBAR_INIT(mb1, 1); }
    __syncthreads();
    const uint32_t tmem = s_tmem;

    // ---- per-thread roles (512 threads) ----
    //   wi/f = tid>>2 in 0..127,  quarter wq = tid&3 (16 j's each)
    const int wi   = tid >> 2;
    const int wq   = tid & 3;
    const float srcI = g_src[row0 + wi];
    const float Pi   = g_P[row0 + wi];
    const float Qi   = g_Q[row0 + wi];
    const bool  uni  = (Pi < 0.f);
    const float rN   = 1.0f / (float)NN;
    const unsigned* mrow = g_mask + (size_t)(row0 + wi) * (NN/32);
    const int mshift = (wq & 1) * 16;              // bit base within mask word
    const __nv_bfloat16* hTh = g_hT_hi + ((size_t)(b*FF + wi)) * NN + wq*16;
    const __nv_bfloat16* hTl = g_hT_lo + ((size_t)(b*FF + wi)) * NN + wq*16;
    const uint32_t tOff0 = (uint32_t)(wi*128 + wq*32);   // row offset in A/B tiles
    const uint32_t sw0 = swz128(tOff0);
    const uint32_t sw1 = swz128(tOff0 + 16);

    int ph0 = 0, ph1 = 0;

    for (int c = 0; c < K3_NCH; ++c) {
        const int buf = c & 1;
        if (c >= 2) {              // chunk c-2's MMAs done reading this buffer
            if (buf == 0) { MBAR_WAIT(mb0, ph0); ph0 ^= 1; }
            else          { MBAR_WAIT(mb1, ph1); ph1 ^= 1; }
        }
        // ---- stage duv slice + B tiles (2+2 uint4 per thread) ----
        if (tid < 64) sduv[buf][tid] = __ldg(&g_duv[b*NN + c*K3_CH + tid]);
        {
            const uint4* sh = (const uint4*)(hTh + c*K3_CH);
            const uint4* sl = (const uint4*)(hTl + c*K3_CH);
            uint4 vh0 = __ldg(&sh[0]), vh1 = __ldg(&sh[1]);
            uint4 vl0 = __ldg(&sl[0]), vl1 = __ldg(&sl[1]);
            *(uint4*)(base + OFF_BHI(buf) + sw0) = vh0;
            *(uint4*)(base + OFF_BHI(buf) + sw1) = vh1;
            *(uint4*)(base + OFF_BLO(buf) + sw0) = vl0;
            *(uint4*)(base + OFF_BLO(buf) + sw1) = vl1;
        }
        __syncthreads();           // sduv ready

        // ---- weight gen -> A tile quarter (16 weights), no exp ----
        {
            const unsigned mw = __ldg(&mrow[c*2 + (wq >> 1)]);
            uint32_t hw[8], lw[8];
            #pragma unroll
            for (int p = 0; p < 8; ++p) {
                const int jj = wq*16 + p*2;          // 0..63 within chunk
                float4 d0 = sduv[buf][jj];
                float4 d1 = sduv[buf][jj + 1];
                float e0 = srcI + d0.x;
                float e1 = srcI + d1.x;
                float w0 = (e0 > 0.f) ? Pi*d0.y : Qi*d0.z;
                float w1 = (e1 > 0.f) ? Pi*d1.y : Qi*d1.z;
                if (uni) { w0 = rN; w1 = rN; }
                if (!((mw >> (mshift + p*2))     & 1u)) w0 = 0.f;
                if (!((mw >> (mshift + p*2 + 1)) & 1u)) w1 = 0.f;
                __nv_bfloat16 h0, l0, h1, l1;
                bf16_split(w0, h0, l0);
                bf16_split(w1, h1, l1);
                hw[p] = pack_bf2(h0, h1);
                lw[p] = pack_bf2(l0, l1);
            }
            *(uint4*)(base + OFF_AHI(buf) + sw0) = make_uint4(hw[0], hw[1], hw[2], hw[3]);
            *(uint4*)(base + OFF_AHI(buf) + sw1) = make_uint4(hw[4], hw[5], hw[6], hw[7]);
            *(uint4*)(base + OFF_ALO(buf) + sw0) = make_uint4(lw[0], lw[1], lw[2], lw[3]);
            *(uint4*)(base + OFF_ALO(buf) + sw1) = make_uint4(lw[4], lw[5], lw[6], lw[7]);
        }
        FENCE_ASYNC();             // generic STS -> async proxy
        __syncthreads();           // all tiles staged

        // ---- 12 MMAs (4 K16-steps x 3 split terms) + commit ----
        if (wid == 0) {
            if (elect_one_pred()) {
                uint64_t ah = make_desc(sb + OFF_AHI(buf));
                uint64_t al = make_desc(sb + OFF_ALO(buf));
                uint64_t bh = make_desc(sb + OFF_BHI(buf));
                uint64_t bl = make_desc(sb + OFF_BLO(buf));
                #pragma unroll
                for (int k = 0; k < 4; ++k) {
                    uint32_t en0 = (c > 0 || k > 0) ? 1u : 0u;
                    mma_f16_ss(tmem, ah + k*2, bh + k*2, K3_IDESC, en0);
                    mma_f16_ss(tmem, ah + k*2, bl + k*2, K3_IDESC, 1u);
                    mma_f16_ss(tmem, al + k*2, bh + k*2, K3_IDESC, 1u);
                }
                TC_COMMIT(buf == 0 ? mb0 : mb1);
            }
        }
    }

    MBAR_WAIT(mb0, ph0);
    MBAR_WAIT(mb1, ph1);
    TC_FENCE_AFTER();

    // ---- epilogue: warps 0-3 read D subpartitions, ELU, store ----
    if (wid < 4) {
        const int m = wid*32 + lid;
        float* orow = out + (size_t)(row0 + m) * FF;
        #pragma unroll
        for (int half = 0; half < 2; ++half) {
            uint32_t dr[64];
            TC_LD_X32(dr,      tmem + half*64);
            TC_LD_X32(dr + 32, tmem + half*64 + 32);
            TC_WAIT_LD();
            #pragma unroll
            for (int c4 = 0; c4 < 16; ++c4) {
                float v0 = __uint_as_float(dr[c4*4+0]);
                float v1 = __uint_as_float(dr[c4*4+1]);
                float v2 = __uint_as_float(dr[c4*4+2]);
                float v3 = __uint_as_float(dr[c4*4+3]);
                v0 = v0 > 0.f ? v0 : (__expf(v0) - 1.f);
                v1 = v1 > 0.f ? v1 : (__expf(v1) - 1.f);
                v2 = v2 > 0.f ? v2 : (__expf(v2) - 1.f);
                v3 = v3 > 0.f ? v3 : (__expf(v3) - 1.f);
                *(float4*)&orow[half*64 + c4*4] = make_float4(v0, v1, v2, v3);
            }
        }
    }
    __syncthreads();
    if (wid == 0) TC_DEALLOC(tmem, 128);

#else  // ---------------- scalar FFMA2 fallback (insurance, 512 thr) --------
    float              (*sh_h)[128] = (float (*)[128])k3_dsm;           // 32x128
    unsigned long long (*sh_wp)[32] =
        (unsigned long long (*)[32])(k3_dsm + 32*128*4);                // 128x32
    __shared__ float sh_P[128], sh_Q[128], sh_src[128];

    const int tid  = threadIdx.x;
    const int row0 = blockIdx.x * 128;
    const int b    = row0 >> 11;
    const int ib   = (tid >> 4) * 4;       // 4-row group (0..124)
    const int f0   = (tid & 15) * 8;
    const int wj   = tid & 31;
    const int wi0  = (tid >> 5) * 8;       // 16 groups x 8 rows = 128
    const float rN = 1.0f / (float)NN;

    if (tid < 128) {
        sh_P[tid]   = g_P[row0 + tid];
        sh_Q[tid]   = g_Q[row0 + tid];
        sh_src[tid] = g_src[row0 + tid];
    }
    unsigned long long acc[4][4];
    #pragma unroll
    for (int r = 0; r < 4; ++r)
        #pragma unroll
        for (int p = 0; p < 4; ++p) acc[r][p] = 0ull;

    for (int jt = 0; jt < NN/32; ++jt) {
        const int j0 = jt * 32;
        __syncthreads();
        const float* hb = g_h + ((size_t)b * NN + j0) * FF;
        #pragma unroll
        for (int v = tid; v < 32*32; v += 512) {
            int j = v >> 5, c4 = v & 31;
            ((float4*)sh_h[j])[c4] = ((const float4*)(hb + (size_t)j * FF))[c4];
        }
        {
            float4 d = __ldg(&g_duv[b * NN + j0 + wj]);
            #pragma unroll
            for (int ii = 0; ii < 8; ++ii) {
                int i = wi0 + ii;
                unsigned mw = __ldg(&g_mask[(size_t)(row0 + i) * (NN/32) + jt]);
                float Pi = sh_P[i];
                float e  = sh_src[i] + d.x;
                float w  = (e > 0.f) ? Pi * d.y : sh_Q[i] * d.z;
                if (Pi < 0.f) w = rN;
                w = ((mw >> wj) & 1u) ? w : 0.f;
                sh_wp[i][wj] = pack2(w, w);
            }
        }
        __syncthreads();
        #pragma unroll 4
        for (int jp = 0; jp < 16; ++jp) {
            const int j = jp * 2;
            ulonglong2 ha0 = *(const ulonglong2*)&sh_h[j][f0];
            ulonglong2 ha1 = *(const ulonglong2*)&sh_h[j][f0 + 4];
            ulonglong2 hb0 = *(const ulonglong2*)&sh_h[j + 1][f0];
            ulonglong2 hb1 = *(const ulonglong2*)&sh_h[j + 1][f0 + 4];
            #pragma unroll
            for (int r = 0; r < 4; ++r) {
                ulonglong2 wp = *(const ulonglong2*)&sh_wp[ib + r][j];
                fma2(acc[r][0], wp.x, ha0.x);
                fma2(acc[r][1], wp.x, ha0.y);
                fma2(acc[r][2], wp.x, ha1.x);
                fma2(acc[r][3], wp.x, ha1.y);
                fma2(acc[r][0], wp.y, hb0.x);
                fma2(acc[r][1], wp.y, hb0.y);
                fma2(acc[r][2], wp.y, hb1.x);
                fma2(acc[r][3], wp.y, hb1.y);
            }
        }
    }
    #pragma unroll
    for (int r = 0; r < 4; ++r) {
        int row = row0 + ib + r;
        float2 p0 = unpack2(acc[r][0]);
        float2 p1 = unpack2(acc[r][1]);
        float2 p2 = unpack2(acc[r][2]);
        float2 p3 = unpack2(acc[r][3]);
        float v[8] = {p0.x, p0.y, p1.x, p1.y, p2.x, p2.y, p3.x, p3.y};
        #pragma unroll
        for (int q = 0; q < 8; ++q)
            v[q] = v[q] > 0.f ? v[q] : (__expf(v[q]) - 1.0f);
        *(float4*)&out[(size_t)row * FF + f0]     = make_float4(v[0], v[1], v[2], v[3]);
        *(float4*)&out[(size_t)row * FF + f0 + 4] = make_float4(v[4], v[5], v[6], v[7]);
    }
#endif
}

// ===========================================================================
extern "C" void kernel_launch(void* const* d_in, const int* in_sizes, int n_in,
                              void* d_out, int out_size) {
    const float* input = (const float*)d_in[0];   // [8,2048,128] f32
    const int*   adj   = (const int*)  d_in[1];   // [8,2048,2048] i32
    const float* W     = (const float*)d_in[2];   // [128,128] f32
    const float* a_src = (const float*)d_in[3];   // [128,1] f32
    const float* a_dst = (const float*)d_in[4];   // [128,1] f32
    float* out = (float*)d_out;                   // [8,2048,128] f32

    static int configured = 0;
    if (!configured) {
        cudaFuncSetAttribute(k3_mma, cudaFuncAttributeMaxDynamicSharedMemorySize,
                             K3_DSM_BYTES);
        configured = 1;
    }

    k1_gemm<<<ROWS/64, 256>>>(input, W, a_src, a_dst);
    k2_stats<<<ROWS/8, 256>>>(adj);
    k3_mma<<<ROWS/128, 512, K3_DSM_BYTES>>>(out);
}

// round 15
// speedup vs baseline: 1.3188x; 1.3188x over previous
#include <cuda_runtime.h>
#include <cuda_bf16.h>
#include <cstdint>

// Problem constants
#define BB 8
#define NN 2048
#define FF 128
#define ROWS (BB*NN)            // 16384
#define ALPHA 0.2f

// tcgen05 is only legal when the VIRTUAL arch is compute_103a/100a-class.
// The harness also compiles a plain compute_103 PTX pass where tcgen05 is
// rejected by ptxas — gate on the arch-feature macros. The #else branch is a
// full scalar fallback: a macro mismatch degrades perf, never correctness.
#if defined(__CUDA_ARCH_FEAT_SM103_ALL) || defined(__CUDA_ARCH_FEAT_SM100_ALL) || \
    defined(__CUDA_ARCH_FEAT_SM101_ALL) || defined(__CUDA_ARCH_FEAT_SM110_ALL)
#define TC_OK 1
#else
#define TC_OK 0
#endif

// ---------------- scratch (static device globals; no allocation) ----------
// g_hT tiles: chunk-blocked, PRE-SWIZZLED (SW128): [b][chunk][128f x 64j bf16]
// tile = 16384 bytes; 8 batches x 32 chunks = 4 MB each.
#define TILE_BYTES 16384
__device__ float    g_h[ROWS * FF];        // 8 MB  h = input @ W^T (f32)
__device__ float    g_src[ROWS];
__device__ float4   g_duv[ROWS];           // {dst, exp(dst), exp(0.2 dst), 0}
__device__ float    g_P[ROWS];             // exp(src)/Z   (-1 flag = uniform row)
__device__ float    g_Q[ROWS];             // exp(0.2 src)/Z
__device__ unsigned g_mask[ROWS * (NN/32)]; // 4 MB adjacency bitmask
__device__ __align__(16) unsigned char g_hT_hi[(size_t)BB * 32 * TILE_BYTES];
__device__ __align__(16) unsigned char g_hT_lo[(size_t)BB * 32 * TILE_BYTES];

// ---------------- packed fp32x2 helpers (FFMA2 — PTX only) ----------------
__device__ __forceinline__ unsigned long long pack2(float x, float y) {
    unsigned long long r;
    asm("mov.b64 %0, {%1, %2};" : "=l"(r) : "f"(x), "f"(y));
    return r;
}
__device__ __forceinline__ void fma2(unsigned long long& d,
                                     unsigned long long a,
                                     unsigned long long b) {
    asm("fma.rn.f32x2 %0, %1, %2, %0;" : "+l"(d) : "l"(a), "l"(b));
}
__device__ __forceinline__ float2 unpack2(unsigned long long v) {
    float2 r;
    asm("mov.b64 {%0, %1}, %2;" : "=f"(r.x), "=f"(r.y) : "l"(v));
    return r;
}

__device__ __forceinline__ uint32_t pack_bf2(__nv_bfloat16 a, __nv_bfloat16 b) {
    __nv_bfloat162 t; t.x = a; t.y = b;
    return *reinterpret_cast<uint32_t*>(&t);
}
__device__ __forceinline__ uint32_t swz128(uint32_t off) {      // SW128 swizzle
    return off ^ ((off >> 3) & 0x70u);
}
__device__ __forceinline__ uint32_t smem_u32(const void* p) {
    uint32_t a;
    asm("{ .reg .u64 t; cvta.to.shared.u64 t, %1; cvt.u32.u64 %0, t; }"
        : "=r"(a) : "l"(p));
    return a;
}
// split f32 -> bf16 hi + bf16 lo (w ~= hi + lo)
__device__ __forceinline__ void bf16_split(float w, __nv_bfloat16& h, __nv_bfloat16& l) {
    h = __float2bfloat16(w);
    l = __float2bfloat16(w - __bfloat162float(h));
}

#if TC_OK
// ---------------- tcgen05 / mbarrier helpers (sm_103a only) ---------------
__device__ __forceinline__ uint32_t elect_one_pred() {
    uint32_t pred;
    asm volatile("{\n\t.reg .pred p;\n\telect.sync _|p, 0xFFFFFFFF;\n\t"
                 "selp.b32 %0, 1, 0, p;\n\t}" : "=r"(pred));
    return pred;
}
#define TC_ALLOC(smem_addr, n) \
    asm volatile("tcgen05.alloc.cta_group::1.sync.aligned.shared::cta.b32 [%0], %1;" \
                 :: "r"(smem_addr), "r"((uint32_t)(n)) : "memory")
#define TC_DEALLOC(tmem, n) \
    asm volatile("tcgen05.dealloc.cta_group::1.sync.aligned.b32 %0, %1;" \
                 :: "r"(tmem), "r"((uint32_t)(n)))
#define TC_COMMIT(mbar) \
    asm volatile("tcgen05.commit.cta_group::1.mbarrier::arrive::one.shared::cluster.b64 [%0];" \
                 :: "r"(mbar) : "memory")
#define TC_FENCE_AFTER() asm volatile("tcgen05.fence::after_thread_sync;" ::: "memory")
#define TC_WAIT_LD()     asm volatile("tcgen05.wait::ld.sync.aligned;" ::: "memory")
#define FENCE_ASYNC()    asm volatile("fence.proxy.async.shared::cta;" ::: "memory")
#define MBAR_INIT(a, n) \
    asm volatile("mbarrier.init.shared.b64 [%0], %1;" :: "r"(a), "r"((uint32_t)(n)) : "memory")
#define MBAR_WAIT(a, ph) do {                                                     \
    uint32_t _m = (a), _p = (ph), _d;                                             \
    asm volatile("{\n\t.reg .pred p;\n\t"                                         \
        "mbarrier.try_wait.parity.acquire.cta.shared::cta.b64 p, [%1], %2;\n\t"   \
        "selp.b32 %0, 1, 0, p;\n\t}" : "=r"(_d) : "r"(_m), "r"(_p) : "memory");   \
    if (!_d) { asm volatile("{\n\t.reg .pred P1;\n\tWL_%=:\n\t"                   \
        "mbarrier.try_wait.parity.acquire.cta.shared::cta.b64 P1, [%0], %1, 0x989680;\n\t" \
        "@P1 bra.uni WD_%=;\n\tbra.uni WL_%=;\n\tWD_%=:\n\t}"                     \
        :: "r"(_m), "r"(_p) : "memory"); }                                        \
} while (0)
#define TC_LD_X32(r, tmem) \
    asm volatile("tcgen05.ld.sync.aligned.32x32b.x32.b32 " \
        "{%0,%1,%2,%3,%4,%5,%6,%7,%8,%9,%10,%11,%12,%13,%14,%15," \
        "%16,%17,%18,%19,%20,%21,%22,%23,%24,%25,%26,%27,%28,%29,%30,%31}, [%32];" \
        : "=r"((r)[0]),"=r"((r)[1]),"=r"((r)[2]),"=r"((r)[3]), \
          "=r"((r)[4]),"=r"((r)[5]),"=r"((r)[6]),"=r"((r)[7]), \
          "=r"((r)[8]),"=r"((r)[9]),"=r"((r)[10]),"=r"((r)[11]), \
          "=r"((r)[12]),"=r"((r)[13]),"=r"((r)[14]),"=r"((r)[15]), \
          "=r"((r)[16]),"=r"((r)[17]),"=r"((r)[18]),"=r"((r)[19]), \
          "=r"((r)[20]),"=r"((r)[21]),"=r"((r)[22]),"=r"((r)[23]), \
          "=r"((r)[24]),"=r"((r)[25]),"=r"((r)[26]),"=r"((r)[27]), \
          "=r"((r)[28]),"=r"((r)[29]),"=r"((r)[30]),"=r"((r)[31]) \
        : "r"(tmem))

static __device__ __forceinline__ uint64_t make_desc(uint32_t addr) {
    const uint64_t BASE = (uint64_t(2) << 61) | (uint64_t(1) << 46)
                        | (uint64_t(64) << 32) | (uint64_t(1) << 16);  // SW128 K-major
    return BASE | ((uint64_t)(addr >> 4) & 0x3FFFull);
}
// SS bf16 MMA, cta_group::1, kind::f16
__device__ __forceinline__ void mma_f16_ss(uint32_t d, uint64_t ad, uint64_t bd,
                                           uint32_t idesc, uint32_t en) {
    asm volatile("{\n\t.reg .pred p;\n\tsetp.ne.u32 p, %5, 0;\n\t"
        "tcgen05.mma.cta_group::1.kind::f16 [%0], %1, %2, %3, {%4, %4, %4, %4}, p;\n\t}"
        :: "r"(d), "l"(ad), "l"(bd), "r"(idesc), "r"(0u), "r"(en) : "memory");
}
// idesc: F32 dtype | BF16 a | BF16 b | N=128 (16<<17) | M=128 (8<<24)
#define K3_IDESC 0x8200490u
#endif  // TC_OK

// ===========================================================================
// Kernel 1: h = input @ W^T, fused with (a) src/dst projections + exp factors
// and (b) the transposed bf16 hi/lo tiles, chunk-blocked + PRE-SWIZZLED.
// Block: 256 threads, tile 64 rows x 128 cols; each block = one j-chunk.
// ===========================================================================
__global__ __launch_bounds__(256) void k1_gemm(const float* __restrict__ input,
                                               const float* __restrict__ W,
                                               const float* __restrict__ a_src,
                                               const float* __restrict__ a_dst) {
    // aliased smem: GEMM phase uses shA(8KB)+shBt(16KB); transpose phase
    // reuses the same region as shT[64][133] (34 KB total static).
    __shared__ __align__(16) unsigned char sraw[64*133*4];
    float (*shA)[32]   = (float (*)[32])sraw;
    float (*shBt)[128] = (float (*)[128])(sraw + 64*32*4);
    float (*shT)[133]  = (float (*)[133])sraw;

    const int tid  = threadIdx.x;
    const int warp = tid >> 5;
    const int lane = tid & 31;
    const int row0 = blockIdx.x * 64;
    const int b    = row0 >> 11;
    const int cc   = (row0 & (NN-1)) >> 6;    // chunk index within batch
    const int c0   = lane * 4;

    unsigned long long acc[8][2];
    #pragma unroll
    for (int r = 0; r < 8; ++r) { acc[r][0] = 0ull; acc[r][1] = 0ull; }

    for (int kc = 0; kc < 4; ++kc) {
        __syncthreads();
        for (int v = tid; v < 64*32; v += 256) {
            int r = v >> 5, k = v & 31;
            shA[r][k] = input[(size_t)(row0 + r) * FF + kc*32 + k];
        }
        for (int v = tid; v < 32*128; v += 256) {
            int c = v & 127, kk = v >> 7;
            shBt[kk][c] = W[(size_t)c * FF + kc*32 + kk];
        }
        __syncthreads();

        #pragma unroll 4
        for (int k = 0; k < 32; ++k) {
            ulonglong2 bv = *(const ulonglong2*)&shBt[k][c0];
            #pragma unroll
            for (int r = 0; r < 8; ++r) {
                float a = shA[warp*8 + r][k];
                unsigned long long ap = pack2(a, a);
                fma2(acc[r][0], ap, bv.x);
                fma2(acc[r][1], ap, bv.y);
            }
        }
    }

    // ---- epilogue A: g_h store + fused projections ----
    const float4 as4 = *(const float4*)&a_src[c0];
    const float4 ad4 = *(const float4*)&a_dst[c0];
    float s1[8], s2[8];
    #pragma unroll
    for (int r = 0; r < 8; ++r) {
        int row = row0 + warp*8 + r;
        float2 p0 = unpack2(acc[r][0]);
        float2 p1 = unpack2(acc[r][1]);
        *(float4*)&g_h[(size_t)row * FF + c0] = make_float4(p0.x, p0.y, p1.x, p1.y);
        s1[r] = p0.x*as4.x + p0.y*as4.y + p1.x*as4.z + p1.y*as4.w;
        s2[r] = p0.x*ad4.x + p0.y*ad4.y + p1.x*ad4.z + p1.y*ad4.w;
    }
    #pragma unroll
    for (int off = 16; off; off >>= 1) {
        #pragma unroll
        for (int r = 0; r < 8; ++r) {
            s1[r] += __shfl_xor_sync(0xffffffffu, s1[r], off);
            s2[r] += __shfl_xor_sync(0xffffffffu, s2[r], off);
        }
    }
    if (lane < 8) {
        int row = row0 + warp*8 + lane;
        float sv = s1[lane], dv = s2[lane];
        g_src[row] = sv;
        g_duv[row] = make_float4(dv, __expf(dv), __expf(ALPHA * dv), 0.f);
    }

    // ---- epilogue B: transpose + bf16 hi/lo split into pre-swizzled tile ----
    __syncthreads();   // all GEMM reads of shA/shBt done; safe to overwrite
    #pragma unroll
    for (int r = 0; r < 8; ++r) {
        int jl = warp*8 + r;
        float2 p0 = unpack2(acc[r][0]);
        float2 p1 = unpack2(acc[r][1]);
        shT[jl][c0 + 0] = p0.x;
        shT[jl][c0 + 1] = p0.y;
        shT[jl][c0 + 2] = p1.x;
        shT[jl][c0 + 3] = p1.y;
    }
    __syncthreads();

    // tile base for (b, cc); write rows f: 128 bytes each, SW128-swizzled.
    unsigned char* tH = g_hT_hi + ((size_t)(b*32 + cc)) * TILE_BYTES;
    unsigned char* tL = g_hT_lo + ((size_t)(b*32 + cc)) * TILE_BYTES;
    const int jq = tid & 3;
    #pragma unroll
    for (int fp = 0; fp < 2; ++fp) {
        const int f = fp*64 + (tid >> 2);
        uint32_t hw[8], lw[8];
        #pragma unroll
        for (int p = 0; p < 8; ++p) {
            float w0 = shT[jq*16 + p*2 + 0][f];
            float w1 = shT[jq*16 + p*2 + 1][f];
            __nv_bfloat16 h0, l0, h1, l1;
            bf16_split(w0, h0, l0);
            bf16_split(w1, h1, l1);
            hw[p] = pack_bf2(h0, h1);
            lw[p] = pack_bf2(l0, l1);
        }
        uint32_t o0 = swz128((uint32_t)(f*128 + jq*32));
        uint32_t o1 = swz128((uint32_t)(f*128 + jq*32 + 16));
        *(uint4*)(tH + o0) = make_uint4(hw[0], hw[1], hw[2], hw[3]);
        *(uint4*)(tH + o1) = make_uint4(hw[4], hw[5], hw[6], hw[7]);
        *(uint4*)(tL + o0) = make_uint4(lw[0], lw[1], lw[2], lw[3]);
        *(uint4*)(tL + o1) = make_uint4(lw[4], lw[5], lw[6], lw[7]);
    }
}

// ===========================================================================
// Kernel 2: adj scan -> bitmask + factorized normalizer (unchanged, proven).
// ===========================================================================
__global__ __launch_bounds__(256) void k2_stats(const int* __restrict__ adj) {
    const int warp = threadIdx.x >> 5;
    const int lane = threadIdx.x & 31;
    const int row  = blockIdx.x * 8 + warp;
    const int b    = row >> 11;
    const int i    = row & (NN-1);

    const int*    arow = adj + ((size_t)b * NN + i) * NN;
    const float4* duvb = g_duv + b * NN;
    const float   srci = g_src[row];

    float su = 0.f, sv = 0.f;
    for (int w = 0; w < NN/32; ++w) {
        int    j  = w*32 + lane;
        int    av = arow[j];
        float4 d  = __ldg(&duvb[j]);
        bool allowed = av > 0;
        unsigned bal = __ballot_sync(0xffffffffu, allowed);
        if (lane == 0) g_mask[(size_t)row * (NN/32) + w] = bal;
        if (allowed) {
            if (srci + d.x > 0.f) su += d.y;
            else                  sv += d.z;
        }
    }
    #pragma unroll
    for (int off = 16; off; off >>= 1) {
        su += __shfl_xor_sync(0xffffffffu, su, off);
        sv += __shfl_xor_sync(0xffffffffu, sv, off);
    }
    float eS  = __expf(srci);
    float eS2 = __expf(ALPHA * srci);
    float Z   = eS * su + eS2 * sv;
    if (lane == 0) {
        if (Z > 0.f) { g_P[row] = eS / Z;  g_Q[row] = eS2 / Z; }
        else         { g_P[row] = -1.f;    g_Q[row] = 0.f;     }
    }
    if (!(Z > 0.f)) {      // isolated row -> uniform over all j
        g_mask[(size_t)row * (NN/32) + lane]      = 0xffffffffu;
        g_mask[(size_t)row * (NN/32) + 32 + lane] = 0xffffffffu;
    }
}

// ===========================================================================
// Kernel 3: out = ELU( att @ h ).  Per CTA: M=128 rows x N=128 feats,
// K=2048 in 64-chunks.  256 threads (R11-proven pipeline).  A = on-the-fly
// weights (bf16 hi+lo), B = pre-swizzled tiles copied CONTIGUOUSLY.
// 3 MMAs per K16-step (hh+hl+lh), fp32 TMEM accum, double-buffered.
// ===========================================================================
#define K3_CH    64                 // K per chunk
#define K3_NCH   (NN/K3_CH)         // 32 chunks
#define K3_BUFSZ 65536              // 4 tiles x 16KB per buffer
#define OFF_AHI(buf) ((buf)*K3_BUFSZ + 0)
#define OFF_ALO(buf) ((buf)*K3_BUFSZ + 16384)
#define OFF_BHI(buf) ((buf)*K3_BUFSZ + 32768)
#define OFF_BLO(buf) ((buf)*K3_BUFSZ + 49152)
#define K3_DSM_BYTES (2*K3_BUFSZ + 1024)

extern __shared__ unsigned char k3_dsm[];

__global__ __launch_bounds__(256) void k3_mma(float* __restrict__ out) {
#if TC_OK
    __shared__ float4   sduv[2][64];
    __shared__ uint32_t s_tmem;
    __shared__ __align__(8) unsigned long long s_mbar[2];

    const int tid  = threadIdx.x;
    const int wid  = tid >> 5;
    const int lid  = tid & 31;
    const int row0 = blockIdx.x * 128;
    const int b    = row0 >> 11;

    uint32_t raw = smem_u32(k3_dsm);
    uint32_t sb  = (raw + 1023) & ~1023u;
    unsigned char* base = k3_dsm + (sb - raw);
    uint32_t mb0 = smem_u32(&s_mbar[0]);
    uint32_t mb1 = smem_u32(&s_mbar[1]);

    if (wid == 0) TC_ALLOC(smem_u32(&s_tmem), 128);
    if (tid == 0) { MBAR_INIT(mb0, 1); MBAR_INIT(mb1, 1); }
    __syncthreads();
    const uint32_t tmem = s_tmem;

    // ---- per-thread roles (256 threads, R11-proven) ----
    // weight gen: i = tid>>1 (row), jh = tid&1 (which 32-j half of the chunk)
    const int wi  = tid >> 1;
    const int wjh = tid & 1;
    const float srcI = g_src[row0 + wi];
    const float Pi   = g_P[row0 + wi];
    const float Qi   = g_Q[row0 + wi];
    const bool  uni  = (Pi < 0.f);
    const float rN   = 1.0f / (float)NN;
    const unsigned* mrow = g_mask + (size_t)(row0 + wi) * (NN/32);
    const uint32_t aRowOff = (uint32_t)(wi*128 + wjh*64);

    int ph0 = 0, ph1 = 0;

    for (int c = 0; c < K3_NCH; ++c) {
        const int buf = c & 1;
        if (c >= 2) {              // chunk c-2's MMAs done reading this buffer
            if (buf == 0) { MBAR_WAIT(mb0, ph0); ph0 ^= 1; }
            else          { MBAR_WAIT(mb1, ph1); ph1 ^= 1; }
        }
        // ---- stage duv slice + B tiles (contiguous pre-swizzled copy) ----
        if (tid < 64) sduv[buf][tid] = __ldg(&g_duv[b*NN + c*K3_CH + tid]);
        {
            const uint4* sH = (const uint4*)(g_hT_hi + ((size_t)(b*32 + c)) * TILE_BYTES);
            const uint4* sL = (const uint4*)(g_hT_lo + ((size_t)(b*32 + c)) * TILE_BYTES);
            uint4* dH = (uint4*)(base + OFF_BHI(buf));
            uint4* dL = (uint4*)(base + OFF_BLO(buf));
            #pragma unroll
            for (int q = 0; q < 4; ++q) {
                int idx = tid + 256*q;           // 1024 uint4 per tile
                dH[idx] = __ldg(&sH[idx]);
                dL[idx] = __ldg(&sL[idx]);
            }
        }
        __syncthreads();           // sduv ready

        // ---- weight gen -> A tiles (hi/lo bf16), no exp ----
        {
            const unsigned mw = __ldg(&mrow[c*2 + wjh]);
            #pragma unroll
            for (int q = 0; q < 4; ++q) {
                uint32_t hw[4], lw[4];
                #pragma unroll
                for (int p = 0; p < 4; ++p) {
                    const int jj = q*8 + p*2;
                    float4 d0 = sduv[buf][wjh*32 + jj];
                    float4 d1 = sduv[buf][wjh*32 + jj + 1];
                    float e0 = srcI + d0.x;
                    float e1 = srcI + d1.x;
                    float w0 = (e0 > 0.f) ? Pi*d0.y : Qi*d0.z;
                    float w1 = (e1 > 0.f) ? Pi*d1.y : Qi*d1.z;
                    if (uni) { w0 = rN; w1 = rN; }
                    if (!((mw >> jj) & 1u))       w0 = 0.f;
                    if (!((mw >> (jj+1)) & 1u))   w1 = 0.f;
                    __nv_bfloat16 h0, l0, h1, l1;
                    bf16_split(w0, h0, l0);
                    bf16_split(w1, h1, l1);
                    hw[p] = pack_bf2(h0, h1);
                    lw[p] = pack_bf2(l0, l1);
                }
                uint32_t off = swz128(aRowOff + q*16);
                *(uint4*)(base + OFF_AHI(buf) + off) = make_uint4(hw[0], hw[1], hw[2], hw[3]);
                *(uint4*)(base + OFF_ALO(buf) + off) = make_uint4(lw[0], lw[1], lw[2], lw[3]);
            }
        }
        FENCE_ASYNC();             // generic STS -> async proxy
        __syncthreads();           // all tiles staged

        // ---- 12 MMAs (4 K16-steps x 3 split terms) + commit ----
        if (wid == 0) {
            if (elect_one_pred()) {
                uint64_t ah = make_desc(sb + OFF_AHI(buf));
                uint64_t al = make_desc(sb + OFF_ALO(buf));
                uint64_t bh = make_desc(sb + OFF_BHI(buf));
                uint64_t bl = make_desc(sb + OFF_BLO(buf));
                #pragma unroll
                for (int k = 0; k < 4; ++k) {
                    uint32_t en0 = (c > 0 || k > 0) ? 1u : 0u;
                    mma_f16_ss(tmem, ah + k*2, bh + k*2, K3_IDESC, en0);
                    mma_f16_ss(tmem, ah + k*2, bl + k*2, K3_IDESC, 1u);
                    mma_f16_ss(tmem, al + k*2, bh + k*2, K3_IDESC, 1u);
                }
                TC_COMMIT(buf == 0 ? mb0 : mb1);
            }
        }
    }

    MBAR_WAIT(mb0, ph0);
    MBAR_WAIT(mb1, ph1);
    TC_FENCE_AFTER();

    // ---- epilogue: warps 0-3 read D subpartitions, ELU, store ----
    if (wid < 4) {
        const int m = wid*32 + lid;
        float* orow = out + (size_t)(row0 + m) * FF;
        #pragma unroll
        for (int half = 0; half < 2; ++half) {
            uint32_t dr[64];
            TC_LD_X32(dr,      tmem + half*64);
            TC_LD_X32(dr + 32, tmem + half*64 + 32);
            TC_WAIT_LD();
            #pragma unroll
            for (int c4 = 0; c4 < 16; ++c4) {
                float v0 = __uint_as_float(dr[c4*4+0]);
                float v1 = __uint_as_float(dr[c4*4+1]);
                float v2 = __uint_as_float(dr[c4*4+2]);
                float v3 = __uint_as_float(dr[c4*4+3]);
                v0 = v0 > 0.f ? v0 : (__expf(v0) - 1.f);
                v1 = v1 > 0.f ? v1 : (__expf(v1) - 1.f);
                v2 = v2 > 0.f ? v2 : (__expf(v2) - 1.f);
                v3 = v3 > 0.f ? v3 : (__expf(v3) - 1.f);
                *(float4*)&orow[half*64 + c4*4] = make_float4(v0, v1, v2, v3);
            }
        }
    }
    __syncthreads();
    if (wid == 0) TC_DEALLOC(tmem, 128);

#else  // ---------------- scalar FFMA2 fallback (insurance, 256 thr) --------
    float              (*sh_h)[128] = (float (*)[128])k3_dsm;           // 32x128
    unsigned long long (*sh_wp)[32] =
        (unsigned long long (*)[32])(k3_dsm + 32*128*4);                // 64x32
    __shared__ float sh_P[64], sh_Q[64], sh_src[64];

    const int tid = threadIdx.x;
    const int b   = (blockIdx.x * 128) >> 11;
    const int ib  = (tid >> 4) * 4;
    const int f0  = (tid & 15) * 8;
    const int wj  = tid & 31;
    const int wi0 = (tid >> 5) * 8;
    const float rN = 1.0f / (float)NN;

    for (int halfM = 0; halfM < 2; ++halfM) {
        const int row0 = blockIdx.x * 128 + halfM * 64;
        __syncthreads();
        if (tid < 64) {
            sh_P[tid]   = g_P[row0 + tid];
            sh_Q[tid]   = g_Q[row0 + tid];
            sh_src[tid] = g_src[row0 + tid];
        }
        unsigned long long acc[4][4];
        #pragma unroll
        for (int r = 0; r < 4; ++r)
            #pragma unroll
            for (int p = 0; p < 4; ++p) acc[r][p] = 0ull;

        for (int jt = 0; jt < NN/32; ++jt) {
            const int j0 = jt * 32;
            __syncthreads();
            const float* hb = g_h + ((size_t)b * NN + j0) * FF;
            #pragma unroll
            for (int v = tid; v < 32*32; v += 256) {
                int j = v >> 5, c4 = v & 31;
                ((float4*)sh_h[j])[c4] = ((const float4*)(hb + (size_t)j * FF))[c4];
            }
            {
                float4 d = __ldg(&g_duv[b * NN + j0 + wj]);
                #pragma unroll
                for (int ii = 0; ii < 8; ++ii) {
                    int i = wi0 + ii;
                    unsigned mw = __ldg(&g_mask[(size_t)(row0 + i) * (NN/32) + jt]);
                    float Pi = sh_P[i];
                    float e  = sh_src[i] + d.x;
                    float w  = (e > 0.f) ? Pi * d.y : sh_Q[i] * d.z;
                    if (Pi < 0.f) w = rN;
                    w = ((mw >> wj) & 1u) ? w : 0.f;
                    sh_wp[i][wj] = pack2(w, w);
                }
            }
            __syncthreads();
            #pragma unroll 4
            for (int jp = 0; jp < 16; ++jp) {
                const int j = jp * 2;
                ulonglong2 ha0 = *(const ulonglong2*)&sh_h[j][f0];
                ulonglong2 ha1 = *(const ulonglong2*)&sh_h[j][f0 + 4];
                ulonglong2 hb0 = *(const ulonglong2*)&sh_h[j + 1][f0];
                ulonglong2 hb1 = *(const ulonglong2*)&sh_h[j + 1][f0 + 4];
                #pragma unroll
                for (int r = 0; r < 4; ++r) {
                    ulonglong2 wp = *(const ulonglong2*)&sh_wp[ib + r][j];
                    fma2(acc[r][0], wp.x, ha0.x);
                    fma2(acc[r][1], wp.x, ha0.y);
                    fma2(acc[r][2], wp.x, ha1.x);
                    fma2(acc[r][3], wp.x, ha1.y);
                    fma2(acc[r][0], wp.y, hb0.x);
                    fma2(acc[r][1], wp.y, hb0.y);
                    fma2(acc[r][2], wp.y, hb1.x);
                    fma2(acc[r][3], wp.y, hb1.y);
                }
            }
        }
        #pragma unroll
        for (int r = 0; r < 4; ++r) {
            int row = row0 + ib + r;
            float2 p0 = unpack2(acc[r][0]);
            float2 p1 = unpack2(acc[r][1]);
            float2 p2 = unpack2(acc[r][2]);
            float2 p3 = unpack2(acc[r][3]);
            float v[8] = {p0.x, p0.y, p1.x, p1.y, p2.x, p2.y, p3.x, p3.y};
            #pragma unroll
            for (int q = 0; q < 8; ++q)
                v[q] = v[q] > 0.f ? v[q] : (__expf(v[q]) - 1.0f);
            *(float4*)&out[(size_t)row * FF + f0]     = make_float4(v[0], v[1], v[2], v[3]);
            *(float4*)&out[(size_t)row * FF + f0 + 4] = make_float4(v[4], v[5], v[6], v[7]);
        }
    }
#endif
}

// ===========================================================================
extern "C" void kernel_launch(void* const* d_in, const int* in_sizes, int n_in,
                              void* d_out, int out_size) {
    const float* input = (const float*)d_in[0];   // [8,2048,128] f32
    const int*   adj   = (const int*)  d_in[1];   // [8,2048,2048] i32
    const float* W     = (const float*)d_in[2];   // [128,128] f32
    const float* a_src = (const float*)d_in[3];   // [128,1] f32
    const float* a_dst = (const float*)d_in[4];   // [128,1] f32
    float* out = (float*)d_out;                   // [8,2048,128] f32

    static int configured = 0;
    if (!configured) {
        cudaFuncSetAttribute(k3_mma, cudaFuncAttributeMaxDynamicSharedMemorySize,
                             K3_DSM_BYTES);
        configured = 1;
    }

    k1_gemm<<<ROWS/64, 256>>>(input, W, a_src, a_dst);
    k2_stats<<<ROWS/8, 256>>>(adj);
    k3_mma<<<ROWS/128, 256, K3_DSM_BYTES>>>(out);
}